// round 5
// baseline (speedup 1.0000x reference)
#include <cuda_runtime.h>
#include <cstdint>

#define L_DIM 1024
#define H_DIM 512
#define C_DIM 8
#define BC_DIM 16

// GEMM tiling
#define BM 128
#define BN 128
#define KC 32                 // k per stage = 4 k8-tiles
#define STAGES 3
#define KSTEPS (H_DIM / KC)   // 16
#define A_STG_FLOATS 4096
#define B_STG_FLOATS 4096
#define STG_FLOATS   8192
#define SMEM_DYN (STAGES * STG_FLOATS * 4)   // 96 KB (>= 128*132*4 epilogue reuse)

// ---- static device scratch ----
__device__ float g_av[BC_DIM * L_DIM];
__device__ float g_bv[BC_DIM * L_DIM];
__device__ float4 g_pa[(size_t)BC_DIM * 64 * 64 * 32];        // [bc][I][KK][lane]
__device__ float2 g_pb[(size_t)BC_DIM * 128 * 64 * 32];       // [bc][J][KK][lane]

// ---------------- helpers ----------------
__device__ __forceinline__ uint32_t cvt_tf32(float x) {
    uint32_t u;
    asm("cvt.rna.tf32.f32 %0, %1;" : "=r"(u) : "f"(x));
    return u;
}
#define CP_ASYNC16(saddr, gaddr) \
    asm volatile("cp.async.cg.shared.global [%0], [%1], 16;" :: "r"(saddr), "l"(gaddr) : "memory")
#define CP_COMMIT() asm volatile("cp.async.commit_group;" ::: "memory")
#define CP_WAIT1()  asm volatile("cp.async.wait_group 1;" ::: "memory")

__device__ __forceinline__ uint32_t smem_u32(const void* p) {
    uint32_t a;
    asm("{ .reg .u64 t; cvta.to.shared.u64 t, %1; cvt.u32.u64 %0, t; }" : "=r"(a) : "l"(p));
    return a;
}
__device__ __forceinline__ void mma_tf32(float* d, const uint32_t* a, const uint32_t* b) {
    asm volatile(
        "mma.sync.aligned.m16n8k8.row.col.f32.tf32.tf32.f32 "
        "{%0,%1,%2,%3}, {%4,%5,%6,%7}, {%8,%9}, {%0,%1,%2,%3};"
        : "+f"(d[0]), "+f"(d[1]), "+f"(d[2]), "+f"(d[3])
        : "r"(a[0]), "r"(a[1]), "r"(a[2]), "r"(a[3]), "r"(b[0]), "r"(b[1]));
}

// ---------------------------------------------------------------------------
// Kernel 1: merged pack. grid (80, 16):
//   x in [0,64):  pack A tile I=x (fragment layout, *v4, tf32) + row dots -> g_av
//   x in [64,80): pack B tiles Jb=x-64 + row dots -> g_bv
// ---------------------------------------------------------------------------
__global__ void pack_kernel(const float* __restrict__ start,
                            const float* __restrict__ endp,
                            const float* __restrict__ v) {
    const int bc = blockIdx.y;
    const int tid = threadIdx.x;
    const int w = tid >> 5, lane = tid & 31;
    const int g = lane >> 2, t = lane & 3;

    if (blockIdx.x < 64) {
        __shared__ float dots[16];
        const int I = blockIdx.x;
        if (tid < 16) dots[tid] = 0.f;
        __syncthreads();
        const float* A = start + (size_t)bc * L_DIM * H_DIM;
        const float* v4 = v + 1536;
        const int r0 = I * 16 + g;
        float4* outp = g_pa + ((size_t)(bc * 64 + I) * 64) * 32;
        float d0 = 0.f, d1 = 0.f;
#pragma unroll
        for (int it = 0; it < 8; it++) {
            int KK = w * 8 + it;
            int c0 = KK * 8 + t;
            float a00 = A[(size_t)r0 * H_DIM + c0];
            float a10 = A[(size_t)(r0 + 8) * H_DIM + c0];
            float a01 = A[(size_t)r0 * H_DIM + c0 + 4];
            float a11 = A[(size_t)(r0 + 8) * H_DIM + c0 + 4];
            float w0 = v[c0] + v[1024 + c0];
            float w1 = v[c0 + 4] + v[1024 + c0 + 4];
            d0 += a00 * w0 + a01 * w1;
            d1 += a10 * w0 + a11 * w1;
            float s0 = v4[c0], s1 = v4[c0 + 4];
            float4 o;
            o.x = __uint_as_float(cvt_tf32(a00 * s0));
            o.y = __uint_as_float(cvt_tf32(a10 * s0));
            o.z = __uint_as_float(cvt_tf32(a01 * s1));
            o.w = __uint_as_float(cvt_tf32(a11 * s1));
            outp[(size_t)KK * 32 + lane] = o;
        }
        atomicAdd(&dots[g], d0);
        atomicAdd(&dots[g + 8], d1);
        __syncthreads();
        if (tid < 16) g_av[bc * L_DIM + I * 16 + tid] = dots[tid];
    } else {
        const int Jb = blockIdx.x - 64;
        const int J = Jb * 8 + w;
        const int row = J * 8 + g;
        const float* B = endp + (size_t)bc * L_DIM * H_DIM + (size_t)row * H_DIM;
        float2* outp = g_pb + ((size_t)(bc * 128 + J) * 64) * 32;
        float d = 0.f;
#pragma unroll
        for (int KK = 0; KK < 64; KK++) {
            int k0 = KK * 8 + t;
            float b0 = B[k0], b1 = B[k0 + 4];
            d += b0 * (v[512 + k0] - v[1024 + k0]) +
                 b1 * (v[512 + k0 + 4] - v[1024 + k0 + 4]);
            float2 o;
            o.x = __uint_as_float(cvt_tf32(b0));
            o.y = __uint_as_float(cvt_tf32(b1));
            outp[(size_t)KK * 32 + lane] = o;
        }
        d += __shfl_xor_sync(0xFFFFFFFFu, d, 1);
        d += __shfl_xor_sync(0xFFFFFFFFu, d, 2);
        if (t == 0) g_bv[bc * L_DIM + row] = d;
    }
}

// ---------------------------------------------------------------------------
// Kernel 2: TF32 mma.sync GEMM, CTA tile 128x128, K=512.
// Direct-write epilogue to out[b,l,m,c] via smem-staged tile.
// grid (16 bc, 8 mtile, 8 ltile) -- bc fastest so the 8 c-CTAs of each
// output sector are co-resident and their partial-sector writes merge in L2.
// ---------------------------------------------------------------------------
__global__ __launch_bounds__(256, 2)
void gemm_mma(float* __restrict__ out) {
    extern __shared__ __align__(16) float smem[];
    __shared__ float av_s[BM], bv_s[BN];

    const int tid = threadIdx.x;
    const int bc = blockIdx.x;
    const int mtile = blockIdx.y * BN;
    const int ltile = blockIdx.z * BM;
    const int Ib = blockIdx.z * 8;
    const int Jb = blockIdx.y * 16;

    if (tid < BM) av_s[tid] = g_av[bc * L_DIM + ltile + tid];
    else          bv_s[tid - BM] = g_bv[bc * L_DIM + mtile + (tid - BM)];

    const uint32_t smem_b = smem_u32(smem);

    const int bA = tid >> 3;
    const int qA = tid & 7;
    const int bB = tid >> 2;
    const int qB = tid & 3;
    const float* paBase = (const float*)g_pa +
        (((size_t)(bc * 64 + Ib + (bA >> 2)) * 64 + (bA & 3)) * 32) * 4 + qA * 16;
    const float* pbBase = (const float*)g_pb +
        (((size_t)(bc * 128 + Jb + (bB >> 2)) * 64 + (bB & 3)) * 32) * 2 + qB * 16;
    const uint32_t sA = smem_b + (bA * 128 + qA * 16) * 4;
    const uint32_t sB = smem_b + (A_STG_FLOATS + bB * 64 + qB * 16) * 4;

#define FILL(S, BUF) do {                                                      \
        const float* _pa = paBase + (size_t)(S) * 4 * 128;                     \
        const float* _pb = pbBase + (size_t)(S) * 4 * 64;                      \
        uint32_t _o = (BUF) * STG_FLOATS * 4;                                  \
        CP_ASYNC16(sA + _o,      _pa);      CP_ASYNC16(sA + _o + 16, _pa + 4); \
        CP_ASYNC16(sA + _o + 32, _pa + 8);  CP_ASYNC16(sA + _o + 48, _pa + 12);\
        CP_ASYNC16(sB + _o,      _pb);      CP_ASYNC16(sB + _o + 16, _pb + 4); \
        CP_ASYNC16(sB + _o + 32, _pb + 8);  CP_ASYNC16(sB + _o + 48, _pb + 12);\
    } while (0)

    FILL(0, 0); CP_COMMIT();
    FILL(1, 1); CP_COMMIT();

    const int wid = tid >> 5, lane = tid & 31;
    const int warp_m = wid >> 2, warp_n = wid & 3;
    const int g = lane >> 2, t = lane & 3;

    float d[4][4][4];
#pragma unroll
    for (int i = 0; i < 4; i++)
#pragma unroll
        for (int j = 0; j < 4; j++)
#pragma unroll
            for (int q = 0; q < 4; q++) d[i][j][q] = 0.f;

    const uint32_t* As = (const uint32_t*)smem;
    const uint32_t* Bs = (const uint32_t*)(smem + A_STG_FLOATS);

    uint32_t afr[2][4][4];
    uint32_t bfr[2][4][2];

#define LOADFRAG(DST, KK, Ab, Bb) do {                                          \
        _Pragma("unroll")                                                       \
        for (int _i = 0; _i < 4; _i++) {                                        \
            const uint4 _va = *(const uint4*)&(Ab)[((warp_m * 4 + _i) * 4 + (KK)) * 128 + lane * 4]; \
            afr[DST][_i][0] = _va.x; afr[DST][_i][1] = _va.y;                   \
            afr[DST][_i][2] = _va.z; afr[DST][_i][3] = _va.w;                   \
        }                                                                       \
        _Pragma("unroll")                                                       \
        for (int _j = 0; _j < 4; _j++) {                                        \
            const uint2 _vb = *(const uint2*)&(Bb)[((warp_n * 4 + _j) * 4 + (KK)) * 64 + lane * 2]; \
            bfr[DST][_j][0] = _vb.x; bfr[DST][_j][1] = _vb.y;                   \
        } } while (0)

    for (int s = 0; s < KSTEPS; s++) {
        const int buf = s % STAGES;
        CP_WAIT1();
        __syncthreads();
        if (s + 2 < KSTEPS) FILL(s + 2, (s + 2) % STAGES);
        CP_COMMIT();

        const uint32_t* Ab = As + buf * STG_FLOATS;
        const uint32_t* Bb = Bs + buf * STG_FLOATS;

        LOADFRAG(0, 0, Ab, Bb);
#pragma unroll
        for (int kk = 0; kk < 4; kk++) {
            const int cur = kk & 1;
            if (kk < 3) LOADFRAG(cur ^ 1, kk + 1, Ab, Bb);
#pragma unroll
            for (int i = 0; i < 4; i++)
#pragma unroll
                for (int j = 0; j < 4; j++)
                    mma_tf32(d[i][j], afr[cur][i], bfr[cur][j]);
        }
    }

    // ---- epilogue: add rank-1 terms, stage tile in smem, direct write ----
    __syncthreads();                 // all warps done reading stage buffers
    float* ep = smem;                // 128 x 132 floats (67.6 KB <= 96 KB)

#pragma unroll
    for (int i = 0; i < 4; i++) {
        const int r0 = warp_m * 64 + i * 16 + g;
        const float av0 = av_s[r0], av1 = av_s[r0 + 8];
#pragma unroll
        for (int j = 0; j < 4; j++) {
            const int lc = warp_n * 32 + j * 8 + t * 2;
            const float bv0 = bv_s[lc], bv1 = bv_s[lc + 1];
            float2 o0, o1;
            o0.x = d[i][j][0] + av0 + bv0;
            o0.y = d[i][j][1] + av0 + bv1;
            o1.x = d[i][j][2] + av1 + bv0;
            o1.y = d[i][j][3] + av1 + bv1;
            *(float2*)&ep[r0 * 132 + lc] = o0;
            *(float2*)&ep[(r0 + 8) * 132 + lc] = o1;
        }
    }
    __syncthreads();

    const int b = bc >> 3, c = bc & 7;
    float* obase = out + (((size_t)b * L_DIM + ltile) * L_DIM + mtile) * C_DIM + c;
#pragma unroll 8
    for (int q = 0; q < 64; q++) {
        int e = q * 256 + tid;       // lane-consecutive m -> 8 lines per STG
        int l = e >> 7, m = e & 127;
        obase[((size_t)l * L_DIM + m) * C_DIM] = ep[l * 132 + m];
    }
}

extern "C" void kernel_launch(void* const* d_in, const int* in_sizes, int n_in,
                              void* d_out, int out_size) {
    const float* start = (const float*)d_in[0];
    const float* endp  = (const float*)d_in[1];
    const float* v     = (const float*)d_in[2];
    float* out = (float*)d_out;

    static bool attr_set = false;
    if (!attr_set) {
        cudaFuncSetAttribute(gemm_mma, cudaFuncAttributeMaxDynamicSharedMemorySize, SMEM_DYN);
        attr_set = true;
    }

    pack_kernel<<<dim3(80, BC_DIM), 256>>>(start, endp, v);
    gemm_mma<<<dim3(BC_DIM, 8, 8), 256, SMEM_DYN>>>(out);
}

// round 6
// speedup vs baseline: 1.9194x; 1.9194x over previous
#include <cuda_runtime.h>
#include <cuda_fp16.h>
#include <cstdint>

#define L_DIM 1024
#define H_DIM 512
#define C_DIM 8
#define BC_DIM 16

// GEMM tiling
#define BM 128
#define BN 128
#define KC 64                 // k floats per stage = 4 K16 mma-tiles
#define STAGES 3
#define KSTEPS (H_DIM / KC)   // 8
#define NKK 32                // K16 tiles over H=512
// stage: A = 8 Itiles * 4 kk * 32 lanes * 16B = 16KB ; B same via uint2 = 16KB
#define A_STG_BYTES 16384
#define STG_BYTES   32768
#define SMEM_DYN (STAGES * STG_BYTES)   // 96 KB

// ---- static device scratch ----
__device__ float g_av[BC_DIM * L_DIM];
__device__ float g_bv[BC_DIM * L_DIM];
__device__ uint4 g_pa[(size_t)BC_DIM * 64 * NKK * 32];   // [bc][I][KK][lane] (8 halves)
__device__ uint2 g_pb[(size_t)BC_DIM * 128 * NKK * 32];  // [bc][J][KK][lane] (4 halves)
__device__ float g_dm[(size_t)BC_DIM * L_DIM * L_DIM];   // [bc][l][m]

// ---------------- helpers ----------------
__device__ __forceinline__ uint32_t h2pack(float a, float b) {
    __half2 h = __floats2half2_rn(a, b);
    return *(uint32_t*)&h;
}
#define CP_ASYNC16(saddr, gaddr) \
    asm volatile("cp.async.cg.shared.global [%0], [%1], 16;" :: "r"(saddr), "l"(gaddr) : "memory")
#define CP_COMMIT() asm volatile("cp.async.commit_group;" ::: "memory")
#define CP_WAIT1()  asm volatile("cp.async.wait_group 1;" ::: "memory")

__device__ __forceinline__ uint32_t smem_u32(const void* p) {
    uint32_t a;
    asm("{ .reg .u64 t; cvta.to.shared.u64 t, %1; cvt.u32.u64 %0, t; }" : "=r"(a) : "l"(p));
    return a;
}
__device__ __forceinline__ void mma_f16(float* d, const uint32_t* a, const uint32_t* b) {
    asm volatile(
        "mma.sync.aligned.m16n8k16.row.col.f32.f16.f16.f32 "
        "{%0,%1,%2,%3}, {%4,%5,%6,%7}, {%8,%9}, {%0,%1,%2,%3};"
        : "+f"(d[0]), "+f"(d[1]), "+f"(d[2]), "+f"(d[3])
        : "r"(a[0]), "r"(a[1]), "r"(a[2]), "r"(a[3]), "r"(b[0]), "r"(b[1]));
}

// ---------------------------------------------------------------------------
// Kernel 1: merged pack (fp16 fragments) + fused rank-1 dots. grid (80, 16).
//   x<64 : A tile I=x  -> g_pa (start*v4 as half2), dots -> g_av
//   x>=64: B tiles Jb  -> g_pb (end as half2),      dots -> g_bv
// ---------------------------------------------------------------------------
__global__ void pack_kernel(const float* __restrict__ start,
                            const float* __restrict__ endp,
                            const float* __restrict__ v) {
    const int bc = blockIdx.y;
    const int tid = threadIdx.x;
    const int w = tid >> 5, lane = tid & 31;
    const int g = lane >> 2, t = lane & 3;

    if (blockIdx.x < 64) {
        __shared__ float dots[16];
        const int I = blockIdx.x;
        if (tid < 16) dots[tid] = 0.f;
        __syncthreads();
        const float* A = start + (size_t)bc * L_DIM * H_DIM;
        const int r0 = I * 16 + g;
        const float* rowA = A + (size_t)r0 * H_DIM;
        const float* rowB = A + (size_t)(r0 + 8) * H_DIM;
        uint4* outp = g_pa + ((size_t)(bc * 64 + I) * NKK) * 32 + lane;
        float d0 = 0.f, d1 = 0.f;
#pragma unroll
        for (int it = 0; it < 4; it++) {
            int KK = w * 4 + it;
            int c0 = KK * 16 + t * 2;
            float2 a00 = *(const float2*)(rowA + c0);
            float2 a10 = *(const float2*)(rowB + c0);
            float2 a01 = *(const float2*)(rowA + c0 + 8);
            float2 a11 = *(const float2*)(rowB + c0 + 8);
            float2 w0, w1, s0, s1;
            w0.x = v[c0]     + v[1024 + c0];     w0.y = v[c0 + 1] + v[1024 + c0 + 1];
            w1.x = v[c0 + 8] + v[1024 + c0 + 8]; w1.y = v[c0 + 9] + v[1024 + c0 + 9];
            s0 = *(const float2*)(v + 1536 + c0);
            s1 = *(const float2*)(v + 1536 + c0 + 8);
            d0 += a00.x * w0.x + a00.y * w0.y + a01.x * w1.x + a01.y * w1.y;
            d1 += a10.x * w0.x + a10.y * w0.y + a11.x * w1.x + a11.y * w1.y;
            uint4 o;
            o.x = h2pack(a00.x * s0.x, a00.y * s0.y);
            o.y = h2pack(a10.x * s0.x, a10.y * s0.y);
            o.z = h2pack(a01.x * s1.x, a01.y * s1.y);
            o.w = h2pack(a11.x * s1.x, a11.y * s1.y);
            outp[(size_t)KK * 32] = o;
        }
        atomicAdd(&dots[g], d0);
        atomicAdd(&dots[g + 8], d1);
        __syncthreads();
        if (tid < 16) g_av[bc * L_DIM + I * 16 + tid] = dots[tid];
    } else {
        const int Jb = blockIdx.x - 64;
        const int J = Jb * 8 + w;
        const int row = J * 8 + g;
        const float* B = endp + (size_t)bc * L_DIM * H_DIM + (size_t)row * H_DIM;
        uint2* outp = g_pb + ((size_t)(bc * 128 + J) * NKK) * 32 + lane;
        float d = 0.f;
#pragma unroll
        for (int KK = 0; KK < NKK; KK++) {
            int k0 = KK * 16 + t * 2;
            float2 b0 = *(const float2*)(B + k0);
            float2 b1 = *(const float2*)(B + k0 + 8);
            d += b0.x * (v[512 + k0]     - v[1024 + k0]) +
                 b0.y * (v[512 + k0 + 1] - v[1024 + k0 + 1]) +
                 b1.x * (v[512 + k0 + 8] - v[1024 + k0 + 8]) +
                 b1.y * (v[512 + k0 + 9] - v[1024 + k0 + 9]);
            uint2 o;
            o.x = h2pack(b0.x, b0.y);
            o.y = h2pack(b1.x, b1.y);
            outp[(size_t)KK * 32] = o;
        }
        d += __shfl_xor_sync(0xFFFFFFFFu, d, 1);
        d += __shfl_xor_sync(0xFFFFFFFFu, d, 2);
        if (t == 0) g_bv[bc * L_DIM + row] = d;
    }
}

// ---------------------------------------------------------------------------
// Kernel 2: FP16 mma.sync GEMM, CTA tile 128x128, K=512, stage K=64.
// grid (8 mtile, 8 ltile, 16 bc), 256 threads (2x4 warps, warp tile 64x32).
// ---------------------------------------------------------------------------
__global__ __launch_bounds__(256, 2)
void gemm_mma(float* __restrict__ dm) {
    extern __shared__ __align__(16) char smem[];
    __shared__ float av_s[BM], bv_s[BN];

    const int tid = threadIdx.x;
    const int bc = blockIdx.z;
    const int mtile = blockIdx.x * BN;
    const int ltile = blockIdx.y * BM;
    const int Ib = blockIdx.y * 8;
    const int Jb = blockIdx.x * 16;

    if (tid < BM) av_s[tid] = g_av[bc * L_DIM + ltile + tid];
    else          bv_s[tid - BM] = g_bv[bc * L_DIM + mtile + (tid - BM)];

    const uint32_t smem_b = smem_u32(smem);

    // --- fill mapping: 4 A chunks + 4 B chunks of 16B per thread per stage ---
    // A chunk ch in [0,1024): Iloc=ch>>7, kk=(ch>>5)&3, ln=ch&31
    // B chunk ch in [0,1024): Jloc=ch>>6, kk=(ch>>4)&3, lp=ch&15 (2 lanes)
    const char* paG[4];
    const char* pbG[4];
    uint32_t sAo[4], sBo[4];
#pragma unroll
    for (int i = 0; i < 4; i++) {
        int ch = tid + 256 * i;
        int Iloc = ch >> 7, kkA = (ch >> 5) & 3, ln = ch & 31;
        paG[i] = (const char*)(g_pa + (((size_t)(bc * 64 + Ib + Iloc) * NKK + kkA) * 32 + ln));
        sAo[i] = smem_b + ch * 16;
        int Jloc = ch >> 6, kkB = (ch >> 4) & 3, lp = ch & 15;
        pbG[i] = (const char*)(g_pb + (((size_t)(bc * 128 + Jb + Jloc) * NKK + kkB) * 32 + 2 * lp));
        sBo[i] = smem_b + A_STG_BYTES + ch * 16;
    }

#define FILL(S, BUF) do {                                                      \
        const size_t _gadv = (size_t)(S) * 4 * 32 * 16;   /* 4 KK x 32 lanes */ \
        const uint32_t _o = (BUF) * STG_BYTES;                                 \
        _Pragma("unroll")                                                      \
        for (int _i = 0; _i < 4; _i++) {                                       \
            CP_ASYNC16(sAo[_i] + _o, paG[_i] + _gadv);                         \
            CP_ASYNC16(sBo[_i] + _o, pbG[_i] + (size_t)(S) * 4 * 32 * 8);      \
        } } while (0)

    FILL(0, 0); CP_COMMIT();
    FILL(1, 1); CP_COMMIT();

    const int wid = tid >> 5, lane = tid & 31;
    const int warp_m = wid >> 2, warp_n = wid & 3;
    const int g = lane >> 2, t = lane & 3;

    float d[4][4][4];
#pragma unroll
    for (int i = 0; i < 4; i++)
#pragma unroll
        for (int j = 0; j < 4; j++)
#pragma unroll
            for (int q = 0; q < 4; q++) d[i][j][q] = 0.f;

    uint32_t afr[2][4][4];
    uint32_t bfr[2][4][2];

#define LOADFRAG(DST, KK, Ab, Bb) do {                                          \
        _Pragma("unroll")                                                       \
        for (int _i = 0; _i < 4; _i++) {                                        \
            const uint4 _va = (Ab)[((warp_m * 4 + _i) * 4 + (KK)) * 32 + lane]; \
            afr[DST][_i][0] = _va.x; afr[DST][_i][1] = _va.y;                   \
            afr[DST][_i][2] = _va.z; afr[DST][_i][3] = _va.w;                   \
        }                                                                       \
        _Pragma("unroll")                                                       \
        for (int _j = 0; _j < 4; _j++) {                                        \
            const uint2 _vb = (Bb)[((warp_n * 4 + _j) * 4 + (KK)) * 32 + lane]; \
            bfr[DST][_j][0] = _vb.x; bfr[DST][_j][1] = _vb.y;                   \
        } } while (0)

    for (int s = 0; s < KSTEPS; s++) {
        const int buf = s % STAGES;
        CP_WAIT1();
        __syncthreads();
        if (s + 2 < KSTEPS) FILL(s + 2, (s + 2) % STAGES);
        CP_COMMIT();

        const uint4* Ab = (const uint4*)(smem + buf * STG_BYTES);
        const uint2* Bb = (const uint2*)(smem + buf * STG_BYTES + A_STG_BYTES);

        LOADFRAG(0, 0, Ab, Bb);
#pragma unroll
        for (int kk = 0; kk < 4; kk++) {
            const int cur = kk & 1;
            if (kk < 3) LOADFRAG(cur ^ 1, kk + 1, Ab, Bb);
#pragma unroll
            for (int i = 0; i < 4; i++)
#pragma unroll
                for (int j = 0; j < 4; j++)
                    mma_f16(d[i][j], afr[cur][i], bfr[cur][j]);
        }
    }

    // epilogue: rank-1 adds, write contiguous dm rows
#pragma unroll
    for (int i = 0; i < 4; i++) {
        const int lr0 = warp_m * 64 + i * 16 + g;
        const float av0 = av_s[lr0], av1 = av_s[lr0 + 8];
        float* row0 = dm + ((size_t)bc * L_DIM + ltile + lr0) * L_DIM + mtile;
        float* row1 = row0 + (size_t)8 * L_DIM;
#pragma unroll
        for (int j = 0; j < 4; j++) {
            const int lc = warp_n * 32 + j * 8 + t * 2;
            const float bv0 = bv_s[lc], bv1 = bv_s[lc + 1];
            float2 o0, o1;
            o0.x = d[i][j][0] + av0 + bv0;
            o0.y = d[i][j][1] + av0 + bv1;
            o1.x = d[i][j][2] + av1 + bv0;
            o1.y = d[i][j][3] + av1 + bv1;
            *(float2*)(row0 + lc) = o0;
            *(float2*)(row1 + lc) = o1;
        }
    }
}

// ---------------------------------------------------------------------------
// Kernel 3: transpose  out[b,l,m,c] = g_dm[b*8+c][l][m]
// ---------------------------------------------------------------------------
__global__ void transpose_kernel(const float* __restrict__ dm, float* __restrict__ out) {
    size_t idx = (size_t)blockIdx.x * blockDim.x + threadIdx.x;
    int m = (int)(idx & 1023);
    int l = (int)((idx >> 10) & 1023);
    int b = (int)(idx >> 20);
    const float* base = dm + ((size_t)b * 8) * 1048576 + (size_t)l * 1024 + m;
    float4 o0, o1;
    o0.x = base[0];
    o0.y = base[1 * 1048576];
    o0.z = base[2 * 1048576];
    o0.w = base[3 * 1048576];
    o1.x = base[4 * 1048576];
    o1.y = base[5 * 1048576];
    o1.z = base[6 * 1048576];
    o1.w = base[7 * 1048576];
    float4* op = (float4*)(out + idx * 8);
    op[0] = o0; op[1] = o1;
}

extern "C" void kernel_launch(void* const* d_in, const int* in_sizes, int n_in,
                              void* d_out, int out_size) {
    const float* start = (const float*)d_in[0];
    const float* endp  = (const float*)d_in[1];
    const float* v     = (const float*)d_in[2];
    float* out = (float*)d_out;

    static bool attr_set = false;
    if (!attr_set) {
        cudaFuncSetAttribute(gemm_mma, cudaFuncAttributeMaxDynamicSharedMemorySize, SMEM_DYN);
        attr_set = true;
    }

    float* dm;
    cudaGetSymbolAddress((void**)&dm, g_dm);

    pack_kernel<<<dim3(80, BC_DIM), 256>>>(start, endp, v);
    gemm_mma<<<dim3(8, 8, BC_DIM), 256, SMEM_DYN>>>(dm);
    transpose_kernel<<<(2u * 1024 * 1024) / 256, 256>>>(dm, out);
}

// round 7
// speedup vs baseline: 2.0505x; 1.0683x over previous
#include <cuda_runtime.h>
#include <cuda_fp16.h>
#include <cstdint>

#define L_DIM 1024
#define H_DIM 512
#define C_DIM 8
#define BC_DIM 16

// GEMM tiling
#define BM 128
#define BN 128
#define KC 64                 // k floats per stage = 4 K16 mma-tiles
#define STAGES 3
#define KSTEPS (H_DIM / KC)   // 8
#define NKK 32                // K16 tiles over H=512
#define A_STG_BYTES 16384
#define STG_BYTES   32768
#define SMEM_DYN (STAGES * STG_BYTES)   // 96 KB

// ---- static device scratch ----
__device__ float g_av[BC_DIM * L_DIM];
__device__ float g_bv[BC_DIM * L_DIM];
__device__ uint4 g_pa[(size_t)BC_DIM * 64 * NKK * 32];   // [bc][I][KK][lane] (8 halves)
__device__ uint2 g_pb[(size_t)BC_DIM * 128 * NKK * 32];  // [bc][J][KK][lane] (4 halves)
__device__ float g_dm[(size_t)BC_DIM * L_DIM * L_DIM];   // [bc][l][m]

// ---------------- helpers ----------------
__device__ __forceinline__ uint32_t h2pack(float a, float b) {
    __half2 h = __floats2half2_rn(a, b);
    return *(uint32_t*)&h;
}
#define CP_ASYNC16(saddr, gaddr) \
    asm volatile("cp.async.cg.shared.global [%0], [%1], 16;" :: "r"(saddr), "l"(gaddr) : "memory")
#define CP_COMMIT() asm volatile("cp.async.commit_group;" ::: "memory")
#define CP_WAIT1()  asm volatile("cp.async.wait_group 1;" ::: "memory")

__device__ __forceinline__ uint32_t smem_u32(const void* p) {
    uint32_t a;
    asm("{ .reg .u64 t; cvta.to.shared.u64 t, %1; cvt.u32.u64 %0, t; }" : "=r"(a) : "l"(p));
    return a;
}
__device__ __forceinline__ void mma_f16(float* d, const uint32_t* a, const uint32_t* b) {
    asm volatile(
        "mma.sync.aligned.m16n8k16.row.col.f32.f16.f16.f32 "
        "{%0,%1,%2,%3}, {%4,%5,%6,%7}, {%8,%9}, {%0,%1,%2,%3};"
        : "+f"(d[0]), "+f"(d[1]), "+f"(d[2]), "+f"(d[3])
        : "r"(a[0]), "r"(a[1]), "r"(a[2]), "r"(a[3]), "r"(b[0]), "r"(b[1]));
}

// ---------------------------------------------------------------------------
// Kernel 1: merged pack (fp16 fragments) + fused rank-1 dots. grid (192, 16).
//   x in [0,64)   : A tile I=x     (start*v4 -> g_pa), dots -> g_av. 4 its/warp.
//   x in [64,192) : B tile J=x-64  (end -> g_pb),      dots -> g_bv. 4 its/warp.
// Balanced work per block.
// ---------------------------------------------------------------------------
__global__ void pack_kernel(const float* __restrict__ start,
                            const float* __restrict__ endp,
                            const float* __restrict__ v) {
    __shared__ float dots[16];
    const int bc = blockIdx.y;
    const int tid = threadIdx.x;
    const int w = tid >> 5, lane = tid & 31;
    const int g = lane >> 2, t = lane & 3;
    if (tid < 16) dots[tid] = 0.f;
    __syncthreads();

    if (blockIdx.x < 64) {
        const int I = blockIdx.x;
        const float* A = start + (size_t)bc * L_DIM * H_DIM;
        const int r0 = I * 16 + g;
        const float* rowA = A + (size_t)r0 * H_DIM;
        const float* rowB = A + (size_t)(r0 + 8) * H_DIM;
        uint4* outp = g_pa + ((size_t)(bc * 64 + I) * NKK) * 32 + lane;
        float d0 = 0.f, d1 = 0.f;
#pragma unroll
        for (int it = 0; it < 4; it++) {
            int KK = w * 4 + it;
            int c0 = KK * 16 + t * 2;
            float2 a00 = *(const float2*)(rowA + c0);
            float2 a10 = *(const float2*)(rowB + c0);
            float2 a01 = *(const float2*)(rowA + c0 + 8);
            float2 a11 = *(const float2*)(rowB + c0 + 8);
            float2 w0, w1, s0, s1;
            w0.x = v[c0]     + v[1024 + c0];     w0.y = v[c0 + 1] + v[1024 + c0 + 1];
            w1.x = v[c0 + 8] + v[1024 + c0 + 8]; w1.y = v[c0 + 9] + v[1024 + c0 + 9];
            s0 = *(const float2*)(v + 1536 + c0);
            s1 = *(const float2*)(v + 1536 + c0 + 8);
            d0 += a00.x * w0.x + a00.y * w0.y + a01.x * w1.x + a01.y * w1.y;
            d1 += a10.x * w0.x + a10.y * w0.y + a11.x * w1.x + a11.y * w1.y;
            uint4 o;
            o.x = h2pack(a00.x * s0.x, a00.y * s0.y);
            o.y = h2pack(a10.x * s0.x, a10.y * s0.y);
            o.z = h2pack(a01.x * s1.x, a01.y * s1.y);
            o.w = h2pack(a11.x * s1.x, a11.y * s1.y);
            outp[(size_t)KK * 32] = o;
        }
        // in-quad reduce, then one atomic per (warp, g)
        d0 += __shfl_xor_sync(0xFFFFFFFFu, d0, 1);
        d0 += __shfl_xor_sync(0xFFFFFFFFu, d0, 2);
        d1 += __shfl_xor_sync(0xFFFFFFFFu, d1, 1);
        d1 += __shfl_xor_sync(0xFFFFFFFFu, d1, 2);
        if (t == 0) { atomicAdd(&dots[g], d0); atomicAdd(&dots[g + 8], d1); }
        __syncthreads();
        if (tid < 16) g_av[bc * L_DIM + I * 16 + tid] = dots[tid];
    } else {
        const int J = blockIdx.x - 64;           // 0..127
        const int row = J * 8 + g;
        const float* B = endp + (size_t)bc * L_DIM * H_DIM + (size_t)row * H_DIM;
        uint2* outp = g_pb + ((size_t)(bc * 128 + J) * NKK) * 32 + lane;
        float d = 0.f;
#pragma unroll
        for (int it = 0; it < 4; it++) {
            int KK = w * 4 + it;
            int k0 = KK * 16 + t * 2;
            float2 b0 = *(const float2*)(B + k0);
            float2 b1 = *(const float2*)(B + k0 + 8);
            d += b0.x * (v[512 + k0]     - v[1024 + k0]) +
                 b0.y * (v[512 + k0 + 1] - v[1024 + k0 + 1]) +
                 b1.x * (v[512 + k0 + 8] - v[1024 + k0 + 8]) +
                 b1.y * (v[512 + k0 + 9] - v[1024 + k0 + 9]);
            uint2 o;
            o.x = h2pack(b0.x, b0.y);
            o.y = h2pack(b1.x, b1.y);
            outp[(size_t)KK * 32] = o;
        }
        d += __shfl_xor_sync(0xFFFFFFFFu, d, 1);
        d += __shfl_xor_sync(0xFFFFFFFFu, d, 2);
        if (t == 0) atomicAdd(&dots[g], d);
        __syncthreads();
        if (tid < 8) g_bv[bc * L_DIM + J * 8 + tid] = dots[tid];
    }
}

// ---------------------------------------------------------------------------
// Kernel 2: FP16 mma.sync GEMM, CTA tile 128x128, K=512, stage K=64.
// grid (8 mtile, 8 ltile, 16 bc), 256 threads (2x4 warps, warp tile 64x32).
// ---------------------------------------------------------------------------
__global__ __launch_bounds__(256, 2)
void gemm_mma(float* __restrict__ dm) {
    extern __shared__ __align__(16) char smem[];
    __shared__ float av_s[BM], bv_s[BN];

    const int tid = threadIdx.x;
    const int bc = blockIdx.z;
    const int mtile = blockIdx.x * BN;
    const int ltile = blockIdx.y * BM;
    const int Ib = blockIdx.y * 8;
    const int Jb = blockIdx.x * 16;

    if (tid < BM) av_s[tid] = g_av[bc * L_DIM + ltile + tid];
    else          bv_s[tid - BM] = g_bv[bc * L_DIM + mtile + (tid - BM)];

    const uint32_t smem_b = smem_u32(smem);

    const char* paG[4];
    const char* pbG[4];
    uint32_t sAo[4], sBo[4];
#pragma unroll
    for (int i = 0; i < 4; i++) {
        int ch = tid + 256 * i;
        int Iloc = ch >> 7, kkA = (ch >> 5) & 3, ln = ch & 31;
        paG[i] = (const char*)(g_pa + (((size_t)(bc * 64 + Ib + Iloc) * NKK + kkA) * 32 + ln));
        sAo[i] = smem_b + ch * 16;
        int Jloc = ch >> 6, kkB = (ch >> 4) & 3, lp = ch & 15;
        pbG[i] = (const char*)(g_pb + (((size_t)(bc * 128 + Jb + Jloc) * NKK + kkB) * 32 + 2 * lp));
        sBo[i] = smem_b + A_STG_BYTES + ch * 16;
    }

#define FILL(S, BUF) do {                                                      \
        const size_t _gadv = (size_t)(S) * 4 * 32 * 16;                        \
        const uint32_t _o = (BUF) * STG_BYTES;                                 \
        _Pragma("unroll")                                                      \
        for (int _i = 0; _i < 4; _i++) {                                       \
            CP_ASYNC16(sAo[_i] + _o, paG[_i] + _gadv);                         \
            CP_ASYNC16(sBo[_i] + _o, pbG[_i] + (size_t)(S) * 4 * 32 * 8);      \
        } } while (0)

    FILL(0, 0); CP_COMMIT();
    FILL(1, 1); CP_COMMIT();

    const int wid = tid >> 5, lane = tid & 31;
    const int warp_m = wid >> 2, warp_n = wid & 3;
    const int g = lane >> 2, t = lane & 3;

    float d[4][4][4];
#pragma unroll
    for (int i = 0; i < 4; i++)
#pragma unroll
        for (int j = 0; j < 4; j++)
#pragma unroll
            for (int q = 0; q < 4; q++) d[i][j][q] = 0.f;

    uint32_t afr[2][4][4];
    uint32_t bfr[2][4][2];

#define LOADFRAG(DST, KK, Ab, Bb) do {                                          \
        _Pragma("unroll")                                                       \
        for (int _i = 0; _i < 4; _i++) {                                        \
            const uint4 _va = (Ab)[((warp_m * 4 + _i) * 4 + (KK)) * 32 + lane]; \
            afr[DST][_i][0] = _va.x; afr[DST][_i][1] = _va.y;                   \
            afr[DST][_i][2] = _va.z; afr[DST][_i][3] = _va.w;                   \
        }                                                                       \
        _Pragma("unroll")                                                       \
        for (int _j = 0; _j < 4; _j++) {                                        \
            const uint2 _vb = (Bb)[((warp_n * 4 + _j) * 4 + (KK)) * 32 + lane]; \
            bfr[DST][_j][0] = _vb.x; bfr[DST][_j][1] = _vb.y;                   \
        } } while (0)

    for (int s = 0; s < KSTEPS; s++) {
        const int buf = s % STAGES;
        CP_WAIT1();
        __syncthreads();
        if (s + 2 < KSTEPS) FILL(s + 2, (s + 2) % STAGES);
        CP_COMMIT();

        const uint4* Ab = (const uint4*)(smem + buf * STG_BYTES);
        const uint2* Bb = (const uint2*)(smem + buf * STG_BYTES + A_STG_BYTES);

        LOADFRAG(0, 0, Ab, Bb);
#pragma unroll
        for (int kk = 0; kk < 4; kk++) {
            const int cur = kk & 1;
            if (kk < 3) LOADFRAG(cur ^ 1, kk + 1, Ab, Bb);
#pragma unroll
            for (int i = 0; i < 4; i++)
#pragma unroll
                for (int j = 0; j < 4; j++)
                    mma_f16(d[i][j], afr[cur][i], bfr[cur][j]);
        }
    }

    // epilogue: rank-1 adds, write contiguous dm rows
#pragma unroll
    for (int i = 0; i < 4; i++) {
        const int lr0 = warp_m * 64 + i * 16 + g;
        const float av0 = av_s[lr0], av1 = av_s[lr0 + 8];
        float* row0 = dm + ((size_t)bc * L_DIM + ltile + lr0) * L_DIM + mtile;
        float* row1 = row0 + (size_t)8 * L_DIM;
#pragma unroll
        for (int j = 0; j < 4; j++) {
            const int lc = warp_n * 32 + j * 8 + t * 2;
            const float bv0 = bv_s[lc], bv1 = bv_s[lc + 1];
            float2 o0, o1;
            o0.x = d[i][j][0] + av0 + bv0;
            o0.y = d[i][j][1] + av0 + bv1;
            o1.x = d[i][j][2] + av1 + bv0;
            o1.y = d[i][j][3] + av1 + bv1;
            *(float2*)(row0 + lc) = o0;
            *(float2*)(row1 + lc) = o1;
        }
    }
}

// ---------------------------------------------------------------------------
// Kernel 3: transpose  out[b,l,m,c] = g_dm[b*8+c][l][m]; 2 m per thread.
// ---------------------------------------------------------------------------
__global__ void transpose_kernel(const float* __restrict__ dm, float* __restrict__ out) {
    size_t e = (size_t)blockIdx.x * blockDim.x + threadIdx.x;   // over b*l*(m/2)
    int m2 = (int)(e & 511) * 2;
    int l  = (int)((e >> 9) & 1023);
    int b  = (int)(e >> 19);
    const float* base = dm + (size_t)b * 8388608 + (size_t)l * 1024 + m2;
    float2 f[8];
#pragma unroll
    for (int c = 0; c < 8; c++) f[c] = *(const float2*)(base + (size_t)c * 1048576);
    float4* op = (float4*)(out + e * 16);
    float4 o;
    o.x = f[0].x; o.y = f[1].x; o.z = f[2].x; o.w = f[3].x; op[0] = o;
    o.x = f[4].x; o.y = f[5].x; o.z = f[6].x; o.w = f[7].x; op[1] = o;
    o.x = f[0].y; o.y = f[1].y; o.z = f[2].y; o.w = f[3].y; op[2] = o;
    o.x = f[4].y; o.y = f[5].y; o.z = f[6].y; o.w = f[7].y; op[3] = o;
}

extern "C" void kernel_launch(void* const* d_in, const int* in_sizes, int n_in,
                              void* d_out, int out_size) {
    const float* start = (const float*)d_in[0];
    const float* endp  = (const float*)d_in[1];
    const float* v     = (const float*)d_in[2];
    float* out = (float*)d_out;

    static bool attr_set = false;
    if (!attr_set) {
        cudaFuncSetAttribute(gemm_mma, cudaFuncAttributeMaxDynamicSharedMemorySize, SMEM_DYN);
        attr_set = true;
    }

    float* dm;
    cudaGetSymbolAddress((void**)&dm, g_dm);

    pack_kernel<<<dim3(192, BC_DIM), 256>>>(start, endp, v);
    gemm_mma<<<dim3(8, 8, BC_DIM), 256, SMEM_DYN>>>(dm);
    transpose_kernel<<<(1u << 20) / 256, 256>>>(dm, out);
}

// round 8
// speedup vs baseline: 2.2821x; 1.1130x over previous
#include <cuda_runtime.h>
#include <cuda_fp16.h>
#include <cstdint>

#define L_DIM 1024
#define H_DIM 512
#define C_DIM 8
#define BC_DIM 16

// GEMM tiling
#define BM 128
#define BN 128
#define STAGES 3
#define KSTEPS 8              // stage K = 64 floats = 4 K16 mma-tiles
#define NKK 32                // K16 tiles over H=512
#define A_STG_BYTES 16384     // 8 tiles * 4 kk * 32 lanes * 16B
#define STG_BYTES   32768
#define SMEM_DYN (STAGES * STG_BYTES)   // 96 KB

// ---- static device scratch ----
__device__ float g_av[BC_DIM * L_DIM];
__device__ float g_bv[BC_DIM * L_DIM];
__device__ uint4 g_pa[(size_t)BC_DIM * 64 * NKK * 32];   // [bc][I][KK][lane] A-frag pairs
__device__ uint4 g_pb[(size_t)BC_DIM * 64 * NKK * 32];   // [bc][Jp][KK][lane] B-frag pairs
__device__ __half g_dm[(size_t)BC_DIM * L_DIM * L_DIM];  // [bc][l][m] fp16

// ---------------- helpers ----------------
__device__ __forceinline__ uint32_t h2pack(float a, float b) {
    __half2 h = __floats2half2_rn(a, b);
    return *(uint32_t*)&h;
}
#define CP_ASYNC16(saddr, gaddr) \
    asm volatile("cp.async.cg.shared.global [%0], [%1], 16;" :: "r"(saddr), "l"(gaddr) : "memory")
#define CP_COMMIT() asm volatile("cp.async.commit_group;" ::: "memory")
#define CP_WAIT1()  asm volatile("cp.async.wait_group 1;" ::: "memory")

__device__ __forceinline__ uint32_t smem_u32(const void* p) {
    uint32_t a;
    asm("{ .reg .u64 t; cvta.to.shared.u64 t, %1; cvt.u32.u64 %0, t; }" : "=r"(a) : "l"(p));
    return a;
}
__device__ __forceinline__ void mma_f16(float* d, const uint32_t* a, const uint32_t* b) {
    asm volatile(
        "mma.sync.aligned.m16n8k16.row.col.f32.f16.f16.f32 "
        "{%0,%1,%2,%3}, {%4,%5,%6,%7}, {%8,%9}, {%0,%1,%2,%3};"
        : "+f"(d[0]), "+f"(d[1]), "+f"(d[2]), "+f"(d[3])
        : "r"(a[0]), "r"(a[1]), "r"(a[2]), "r"(a[3]), "r"(b[0]), "r"(b[1]));
}

// ---------------------------------------------------------------------------
// Kernel 1: symmetric pack + fused rank-1 dots. grid (128, 16).
//   x in [0,64)  : A tile I=x   (start*v4 -> g_pa), dots -> g_av
//   x in [64,128): B pair Jp    (end -> g_pb),      dots -> g_bv
// Both paths: 16 rows, warp w handles KK = w*4..w*4+3.
// ---------------------------------------------------------------------------
__global__ void pack_kernel(const float* __restrict__ start,
                            const float* __restrict__ endp,
                            const float* __restrict__ v) {
    __shared__ float dots[16];
    const int bc = blockIdx.y;
    const int tid = threadIdx.x;
    const int w = tid >> 5, lane = tid & 31;
    const int g = lane >> 2, t = lane & 3;
    if (tid < 16) dots[tid] = 0.f;
    __syncthreads();

    const bool isA = (blockIdx.x < 64);
    const int T = isA ? blockIdx.x : blockIdx.x - 64;     // I or Jp
    const float* src = isA ? start : endp;
    const int r0 = T * 16 + g;
    const float* row0 = src + (size_t)bc * L_DIM * H_DIM + (size_t)r0 * H_DIM;
    const float* row1 = row0 + (size_t)8 * H_DIM;
    uint4* outp = (isA ? g_pa : g_pb) + ((size_t)(bc * 64 + T) * NKK) * 32 + lane;

    float d0 = 0.f, d1 = 0.f;
#pragma unroll
    for (int it = 0; it < 4; it++) {
        int KK = w * 4 + it;
        int c0 = KK * 16 + t * 2;
        float2 x00 = *(const float2*)(row0 + c0);
        float2 x01 = *(const float2*)(row0 + c0 + 8);
        float2 x10 = *(const float2*)(row1 + c0);
        float2 x11 = *(const float2*)(row1 + c0 + 8);
        float2 w0, w1;
        if (isA) {
            w0.x = v[c0]     + v[1024 + c0];     w0.y = v[c0 + 1] + v[1024 + c0 + 1];
            w1.x = v[c0 + 8] + v[1024 + c0 + 8]; w1.y = v[c0 + 9] + v[1024 + c0 + 9];
        } else {
            w0.x = v[512 + c0]     - v[1024 + c0];     w0.y = v[512 + c0 + 1] - v[1024 + c0 + 1];
            w1.x = v[512 + c0 + 8] - v[1024 + c0 + 8]; w1.y = v[512 + c0 + 9] - v[1024 + c0 + 9];
        }
        d0 += x00.x * w0.x + x00.y * w0.y + x01.x * w1.x + x01.y * w1.y;
        d1 += x10.x * w0.x + x10.y * w0.y + x11.x * w1.x + x11.y * w1.y;
        uint4 o;
        if (isA) {
            float2 s0 = *(const float2*)(v + 1536 + c0);
            float2 s1 = *(const float2*)(v + 1536 + c0 + 8);
            // A frag order: {row g @k0, row g+8 @k0, row g @k0+8, row g+8 @k0+8}
            o.x = h2pack(x00.x * s0.x, x00.y * s0.y);
            o.y = h2pack(x10.x * s0.x, x10.y * s0.y);
            o.z = h2pack(x01.x * s1.x, x01.y * s1.y);
            o.w = h2pack(x11.x * s1.x, x11.y * s1.y);
        } else {
            // B pair order: {frag j: @k0, @k0+8 ; frag j+1: @k0, @k0+8}
            o.x = h2pack(x00.x, x00.y);
            o.y = h2pack(x01.x, x01.y);
            o.z = h2pack(x10.x, x10.y);
            o.w = h2pack(x11.x, x11.y);
        }
        outp[(size_t)KK * 32] = o;
    }
    d0 += __shfl_xor_sync(0xFFFFFFFFu, d0, 1);
    d0 += __shfl_xor_sync(0xFFFFFFFFu, d0, 2);
    d1 += __shfl_xor_sync(0xFFFFFFFFu, d1, 1);
    d1 += __shfl_xor_sync(0xFFFFFFFFu, d1, 2);
    if (t == 0) { atomicAdd(&dots[g], d0); atomicAdd(&dots[g + 8], d1); }
    __syncthreads();
    if (tid < 16) {
        float* dst = isA ? g_av : g_bv;
        dst[bc * L_DIM + T * 16 + tid] = dots[tid];
    }
}

// ---------------------------------------------------------------------------
// Kernel 2: FP16 mma.sync GEMM, CTA tile 128x128, K=512, stage K=64.
// grid (8 mtile, 8 ltile, 16 bc), 256 threads (2x4 warps, warp tile 64x32).
// All shared loads are LDS.128. Output -> fp16 dm.
// ---------------------------------------------------------------------------
__global__ __launch_bounds__(256, 2)
void gemm_mma(__half* __restrict__ dm) {
    extern __shared__ __align__(16) char smem[];
    __shared__ float av_s[BM], bv_s[BN];

    const int tid = threadIdx.x;
    const int bc = blockIdx.z;
    const int mtile = blockIdx.x * BN;
    const int ltile = blockIdx.y * BM;
    const int Ib = blockIdx.y * 8;
    const int Jbp = blockIdx.x * 8;

    if (tid < BM) av_s[tid] = g_av[bc * L_DIM + ltile + tid];
    else          bv_s[tid - BM] = g_bv[bc * L_DIM + mtile + (tid - BM)];

    const uint32_t smem_b = smem_u32(smem);

    // symmetric chunk mapping: ch -> (tile ch>>7, kk (ch>>5)&3, lane ch&31)
    const char* paG[4];
    const char* pbG[4];
    uint32_t sAo[4], sBo[4];
#pragma unroll
    for (int i = 0; i < 4; i++) {
        int ch = tid + 256 * i;
        int Tl = ch >> 7, kk = (ch >> 5) & 3, ln = ch & 31;
        paG[i] = (const char*)(g_pa + (((size_t)(bc * 64 + Ib + Tl) * NKK + kk) * 32 + ln));
        pbG[i] = (const char*)(g_pb + (((size_t)(bc * 64 + Jbp + Tl) * NKK + kk) * 32 + ln));
        sAo[i] = smem_b + ch * 16;
        sBo[i] = smem_b + A_STG_BYTES + ch * 16;
    }

#define FILL(S, BUF) do {                                                      \
        const size_t _gadv = (size_t)(S) * 2048;   /* 4 kk x 32 lanes x 16B */ \
        const uint32_t _o = (BUF) * STG_BYTES;                                 \
        _Pragma("unroll")                                                      \
        for (int _i = 0; _i < 4; _i++) {                                       \
            CP_ASYNC16(sAo[_i] + _o, paG[_i] + _gadv);                         \
            CP_ASYNC16(sBo[_i] + _o, pbG[_i] + _gadv);                         \
        } } while (0)

    FILL(0, 0); CP_COMMIT();
    FILL(1, 1); CP_COMMIT();

    const int wid = tid >> 5, lane = tid & 31;
    const int warp_m = wid >> 2, warp_n = wid & 3;
    const int g = lane >> 2, t = lane & 3;

    float d[4][4][4];
#pragma unroll
    for (int i = 0; i < 4; i++)
#pragma unroll
        for (int j = 0; j < 4; j++)
#pragma unroll
            for (int q = 0; q < 4; q++) d[i][j][q] = 0.f;

    uint32_t afr[2][4][4];
    uint32_t bfr[2][4][2];

#define LOADFRAG(DST, KK, Ab, Bb) do {                                          \
        _Pragma("unroll")                                                       \
        for (int _i = 0; _i < 4; _i++) {                                        \
            const uint4 _va = (Ab)[((warp_m * 4 + _i) * 4 + (KK)) * 32 + lane]; \
            afr[DST][_i][0] = _va.x; afr[DST][_i][1] = _va.y;                   \
            afr[DST][_i][2] = _va.z; afr[DST][_i][3] = _va.w;                   \
        }                                                                       \
        _Pragma("unroll")                                                       \
        for (int _jp = 0; _jp < 2; _jp++) {                                     \
            const uint4 _vb = (Bb)[((warp_n * 2 + _jp) * 4 + (KK)) * 32 + lane];\
            bfr[DST][2*_jp][0]   = _vb.x; bfr[DST][2*_jp][1]   = _vb.y;         \
            bfr[DST][2*_jp+1][0] = _vb.z; bfr[DST][2*_jp+1][1] = _vb.w;         \
        } } while (0)

    for (int s = 0; s < KSTEPS; s++) {
        const int buf = s % STAGES;
        CP_WAIT1();
        __syncthreads();
        if (s + 2 < KSTEPS) FILL(s + 2, (s + 2) % STAGES);
        CP_COMMIT();

        const uint4* Ab = (const uint4*)(smem + buf * STG_BYTES);
        const uint4* Bb = (const uint4*)(smem + buf * STG_BYTES + A_STG_BYTES);

        LOADFRAG(0, 0, Ab, Bb);
#pragma unroll
        for (int kk = 0; kk < 4; kk++) {
            const int cur = kk & 1;
            if (kk < 3) LOADFRAG(cur ^ 1, kk + 1, Ab, Bb);
#pragma unroll
            for (int i = 0; i < 4; i++)
#pragma unroll
                for (int j = 0; j < 4; j++)
                    mma_f16(d[i][j], afr[cur][i], bfr[cur][j]);
        }
    }

    // epilogue: rank-1 adds, fp16 convert, write contiguous dm rows
#pragma unroll
    for (int i = 0; i < 4; i++) {
        const int lr0 = warp_m * 64 + i * 16 + g;
        const float av0 = av_s[lr0], av1 = av_s[lr0 + 8];
        __half* row0 = dm + ((size_t)bc * L_DIM + ltile + lr0) * L_DIM + mtile;
        __half* row1 = row0 + (size_t)8 * L_DIM;
#pragma unroll
        for (int j = 0; j < 4; j++) {
            const int lc = warp_n * 32 + j * 8 + t * 2;
            const float bv0 = bv_s[lc], bv1 = bv_s[lc + 1];
            *(__half2*)(row0 + lc) = __floats2half2_rn(d[i][j][0] + av0 + bv0,
                                                       d[i][j][1] + av0 + bv1);
            *(__half2*)(row1 + lc) = __floats2half2_rn(d[i][j][2] + av1 + bv0,
                                                       d[i][j][3] + av1 + bv1);
        }
    }
}

// ---------------------------------------------------------------------------
// Kernel 3: transpose  out[b,l,m,c] = float(g_dm[b*8+c][l][m]); 2 m per thread.
// ---------------------------------------------------------------------------
__global__ void transpose_kernel(const __half* __restrict__ dm, float* __restrict__ out) {
    size_t e = (size_t)blockIdx.x * blockDim.x + threadIdx.x;   // over b*l*(m/2)
    int m2 = (int)(e & 511) * 2;
    int l  = (int)((e >> 9) & 1023);
    int b  = (int)(e >> 19);
    const __half* base = dm + (size_t)b * 8388608 + (size_t)l * 1024 + m2;
    float2 f[8];
#pragma unroll
    for (int c = 0; c < 8; c++)
        f[c] = __half22float2(*(const __half2*)(base + (size_t)c * 1048576));
    float4* op = (float4*)(out + e * 16);
    float4 o;
    o.x = f[0].x; o.y = f[1].x; o.z = f[2].x; o.w = f[3].x; op[0] = o;
    o.x = f[4].x; o.y = f[5].x; o.z = f[6].x; o.w = f[7].x; op[1] = o;
    o.x = f[0].y; o.y = f[1].y; o.z = f[2].y; o.w = f[3].y; op[2] = o;
    o.x = f[4].y; o.y = f[5].y; o.z = f[6].y; o.w = f[7].y; op[3] = o;
}

extern "C" void kernel_launch(void* const* d_in, const int* in_sizes, int n_in,
                              void* d_out, int out_size) {
    const float* start = (const float*)d_in[0];
    const float* endp  = (const float*)d_in[1];
    const float* v     = (const float*)d_in[2];
    float* out = (float*)d_out;

    static bool attr_set = false;
    if (!attr_set) {
        cudaFuncSetAttribute(gemm_mma, cudaFuncAttributeMaxDynamicSharedMemorySize, SMEM_DYN);
        attr_set = true;
    }

    __half* dm;
    cudaGetSymbolAddress((void**)&dm, g_dm);

    pack_kernel<<<dim3(128, BC_DIM), 256>>>(start, endp, v);
    gemm_mma<<<dim3(8, 8, BC_DIM), 256, SMEM_DYN>>>(dm);
    transpose_kernel<<<(1u << 20) / 256, 256>>>(dm, out);
}

// round 9
// speedup vs baseline: 2.2927x; 1.0046x over previous
#include <cuda_runtime.h>
#include <cuda_fp16.h>
#include <cstdint>

#define L_DIM 1024
#define H_DIM 512
#define C_DIM 8
#define BC_DIM 16

// GEMM tiling
#define BM 128
#define BN 128
#define STAGES 3
#define KSTEPS 8              // stage K = 64 floats = 4 K16 mma-tiles
#define NKK 32                // K16 tiles over H=512
#define A_STG_BYTES 16384
#define STG_BYTES   32768
#define SMEM_DYN (STAGES * STG_BYTES)   // 96 KB

#define PSTRIDE 520           // pack stage row stride (8-float pad)

// ---- static device scratch ----
__device__ float g_av[BC_DIM * L_DIM];
__device__ float g_bv[BC_DIM * L_DIM];
__device__ uint4 g_pa[(size_t)BC_DIM * 64 * NKK * 32];   // [bc][I][KK][lane] A-frag pairs
__device__ uint4 g_pb[(size_t)BC_DIM * 64 * NKK * 32];   // [bc][Jp][KK][lane] B-frag pairs
__device__ __half g_dm[(size_t)BC_DIM * L_DIM * L_DIM];  // [bc][l][m] fp16

// ---------------- helpers ----------------
__device__ __forceinline__ uint32_t h2pack(float a, float b) {
    __half2 h = __floats2half2_rn(a, b);
    return *(uint32_t*)&h;
}
#define CP_ASYNC16(saddr, gaddr) \
    asm volatile("cp.async.cg.shared.global [%0], [%1], 16;" :: "r"(saddr), "l"(gaddr) : "memory")
#define CP_COMMIT() asm volatile("cp.async.commit_group;" ::: "memory")
#define CP_WAIT1()  asm volatile("cp.async.wait_group 1;" ::: "memory")

__device__ __forceinline__ uint32_t smem_u32(const void* p) {
    uint32_t a;
    asm("{ .reg .u64 t; cvta.to.shared.u64 t, %1; cvt.u32.u64 %0, t; }" : "=r"(a) : "l"(p));
    return a;
}
__device__ __forceinline__ void mma_f16(float* d, const uint32_t* a, const uint32_t* b) {
    asm volatile(
        "mma.sync.aligned.m16n8k16.row.col.f32.f16.f16.f32 "
        "{%0,%1,%2,%3}, {%4,%5,%6,%7}, {%8,%9}, {%0,%1,%2,%3};"
        : "+f"(d[0]), "+f"(d[1]), "+f"(d[2]), "+f"(d[3])
        : "r"(a[0]), "r"(a[1]), "r"(a[2]), "r"(a[3]), "r"(b[0]), "r"(b[1]));
}

// ---------------------------------------------------------------------------
// Kernel 1: symmetric pack + fused rank-1 dots, smem-staged coalesced loads.
// grid (128, 16): x<64 -> A tile I=x ; x>=64 -> B pair Jp=x-64.
// ---------------------------------------------------------------------------
__global__ void pack_kernel(const float* __restrict__ start,
                            const float* __restrict__ endp,
                            const float* __restrict__ v) {
    __shared__ float stage[16 * PSTRIDE];
    __shared__ float dots[16];
    const int bc = blockIdx.y;
    const int tid = threadIdx.x;
    const int w = tid >> 5, lane = tid & 31;
    const int g = lane >> 2, t = lane & 3;

    const bool isA = (blockIdx.x < 64);
    const int T = isA ? blockIdx.x : blockIdx.x - 64;     // I or Jp
    const float* src = (isA ? start : endp) +
                       (size_t)bc * L_DIM * H_DIM + (size_t)(T * 16) * H_DIM;

    // stage 16 rows x 512 floats, fully coalesced LDG.128
#pragma unroll
    for (int i = 0; i < 8; i++) {
        int idx = tid + 256 * i;          // float4 index over [16][128]
        int r = idx >> 7, c4 = idx & 127;
        *(float4*)&stage[r * PSTRIDE + c4 * 4] =
            *(const float4*)(src + (size_t)r * H_DIM + c4 * 4);
    }
    if (tid < 16) dots[tid] = 0.f;
    __syncthreads();

    const float* row0 = &stage[g * PSTRIDE];
    const float* row1 = &stage[(g + 8) * PSTRIDE];
    uint4* outp = (isA ? g_pa : g_pb) + ((size_t)(bc * 64 + T) * NKK) * 32 + lane;

    float d0 = 0.f, d1 = 0.f;
#pragma unroll
    for (int it = 0; it < 4; it++) {
        int KK = w * 4 + it;
        int c0 = KK * 16 + t * 2;
        float2 x00 = *(const float2*)(row0 + c0);
        float2 x01 = *(const float2*)(row0 + c0 + 8);
        float2 x10 = *(const float2*)(row1 + c0);
        float2 x11 = *(const float2*)(row1 + c0 + 8);
        float2 w0, w1;
        if (isA) {
            w0.x = v[c0]     + v[1024 + c0];     w0.y = v[c0 + 1] + v[1024 + c0 + 1];
            w1.x = v[c0 + 8] + v[1024 + c0 + 8]; w1.y = v[c0 + 9] + v[1024 + c0 + 9];
        } else {
            w0.x = v[512 + c0]     - v[1024 + c0];     w0.y = v[512 + c0 + 1] - v[1024 + c0 + 1];
            w1.x = v[512 + c0 + 8] - v[1024 + c0 + 8]; w1.y = v[512 + c0 + 9] - v[1024 + c0 + 9];
        }
        d0 += x00.x * w0.x + x00.y * w0.y + x01.x * w1.x + x01.y * w1.y;
        d1 += x10.x * w0.x + x10.y * w0.y + x11.x * w1.x + x11.y * w1.y;
        uint4 o;
        if (isA) {
            float2 s0 = *(const float2*)(v + 1536 + c0);
            float2 s1 = *(const float2*)(v + 1536 + c0 + 8);
            o.x = h2pack(x00.x * s0.x, x00.y * s0.y);
            o.y = h2pack(x10.x * s0.x, x10.y * s0.y);
            o.z = h2pack(x01.x * s1.x, x01.y * s1.y);
            o.w = h2pack(x11.x * s1.x, x11.y * s1.y);
        } else {
            o.x = h2pack(x00.x, x00.y);
            o.y = h2pack(x01.x, x01.y);
            o.z = h2pack(x10.x, x10.y);
            o.w = h2pack(x11.x, x11.y);
        }
        outp[(size_t)KK * 32] = o;
    }
    d0 += __shfl_xor_sync(0xFFFFFFFFu, d0, 1);
    d0 += __shfl_xor_sync(0xFFFFFFFFu, d0, 2);
    d1 += __shfl_xor_sync(0xFFFFFFFFu, d1, 1);
    d1 += __shfl_xor_sync(0xFFFFFFFFu, d1, 2);
    if (t == 0) { atomicAdd(&dots[g], d0); atomicAdd(&dots[g + 8], d1); }
    __syncthreads();
    if (tid < 16) {
        float* dst = isA ? g_av : g_bv;
        dst[bc * L_DIM + T * 16 + tid] = dots[tid];
    }
}

// ---------------------------------------------------------------------------
// Kernel 2: FP16 mma.sync GEMM, CTA tile 128x128, K=512, stage K=64.
// grid (8 mtile, 8 ltile, 16 bc), 256 threads (2x4 warps, warp tile 64x32).
// ---------------------------------------------------------------------------
__global__ __launch_bounds__(256, 2)
void gemm_mma(__half* __restrict__ dm) {
    extern __shared__ __align__(16) char smem[];
    __shared__ float av_s[BM], bv_s[BN];

    const int tid = threadIdx.x;
    const int bc = blockIdx.z;
    const int mtile = blockIdx.x * BN;
    const int ltile = blockIdx.y * BM;
    const int Ib = blockIdx.y * 8;
    const int Jbp = blockIdx.x * 8;

    const uint32_t smem_b = smem_u32(smem);

    const char* paG[4];
    const char* pbG[4];
    uint32_t sAo[4], sBo[4];
#pragma unroll
    for (int i = 0; i < 4; i++) {
        int ch = tid + 256 * i;
        int Tl = ch >> 7, kk = (ch >> 5) & 3, ln = ch & 31;
        paG[i] = (const char*)(g_pa + (((size_t)(bc * 64 + Ib + Tl) * NKK + kk) * 32 + ln));
        pbG[i] = (const char*)(g_pb + (((size_t)(bc * 64 + Jbp + Tl) * NKK + kk) * 32 + ln));
        sAo[i] = smem_b + ch * 16;
        sBo[i] = smem_b + A_STG_BYTES + ch * 16;
    }

#define FILL(S, BUF) do {                                                      \
        const size_t _gadv = (size_t)(S) * 2048;                               \
        const uint32_t _o = (BUF) * STG_BYTES;                                 \
        _Pragma("unroll")                                                      \
        for (int _i = 0; _i < 4; _i++) {                                       \
            CP_ASYNC16(sAo[_i] + _o, paG[_i] + _gadv);                         \
            CP_ASYNC16(sBo[_i] + _o, pbG[_i] + _gadv);                         \
        } } while (0)

    FILL(0, 0); CP_COMMIT();
    FILL(1, 1); CP_COMMIT();

    // rank-1 vectors loaded after the pipeline is primed
    if (tid < BM) av_s[tid] = g_av[bc * L_DIM + ltile + tid];
    else          bv_s[tid - BM] = g_bv[bc * L_DIM + mtile + (tid - BM)];

    const int wid = tid >> 5, lane = tid & 31;
    const int warp_m = wid >> 2, warp_n = wid & 3;
    const int g = lane >> 2, t = lane & 3;

    float d[4][4][4];
#pragma unroll
    for (int i = 0; i < 4; i++)
#pragma unroll
        for (int j = 0; j < 4; j++)
#pragma unroll
            for (int q = 0; q < 4; q++) d[i][j][q] = 0.f;

    uint32_t afr[2][4][4];
    uint32_t bfr[2][4][2];

#define LOADFRAG(DST, KK, Ab, Bb) do {                                          \
        _Pragma("unroll")                                                       \
        for (int _i = 0; _i < 4; _i++) {                                        \
            const uint4 _va = (Ab)[((warp_m * 4 + _i) * 4 + (KK)) * 32 + lane]; \
            afr[DST][_i][0] = _va.x; afr[DST][_i][1] = _va.y;                   \
            afr[DST][_i][2] = _va.z; afr[DST][_i][3] = _va.w;                   \
        }                                                                       \
        _Pragma("unroll")                                                       \
        for (int _jp = 0; _jp < 2; _jp++) {                                     \
            const uint4 _vb = (Bb)[((warp_n * 2 + _jp) * 4 + (KK)) * 32 + lane];\
            bfr[DST][2*_jp][0]   = _vb.x; bfr[DST][2*_jp][1]   = _vb.y;         \
            bfr[DST][2*_jp+1][0] = _vb.z; bfr[DST][2*_jp+1][1] = _vb.w;         \
        } } while (0)

    for (int s = 0; s < KSTEPS; s++) {
        const int buf = s % STAGES;
        CP_WAIT1();
        __syncthreads();
        if (s + 2 < KSTEPS) FILL(s + 2, (s + 2) % STAGES);
        CP_COMMIT();

        const uint4* Ab = (const uint4*)(smem + buf * STG_BYTES);
        const uint4* Bb = (const uint4*)(smem + buf * STG_BYTES + A_STG_BYTES);

        LOADFRAG(0, 0, Ab, Bb);
#pragma unroll
        for (int kk = 0; kk < 4; kk++) {
            const int cur = kk & 1;
            if (kk < 3) LOADFRAG(cur ^ 1, kk + 1, Ab, Bb);
#pragma unroll
            for (int i = 0; i < 4; i++)
#pragma unroll
                for (int j = 0; j < 4; j++)
                    mma_f16(d[i][j], afr[cur][i], bfr[cur][j]);
        }
    }

    // epilogue: rank-1 adds, fp16 convert, write contiguous dm rows
#pragma unroll
    for (int i = 0; i < 4; i++) {
        const int lr0 = warp_m * 64 + i * 16 + g;
        const float av0 = av_s[lr0], av1 = av_s[lr0 + 8];
        __half* row0 = dm + ((size_t)bc * L_DIM + ltile + lr0) * L_DIM + mtile;
        __half* row1 = row0 + (size_t)8 * L_DIM;
#pragma unroll
        for (int j = 0; j < 4; j++) {
            const int lc = warp_n * 32 + j * 8 + t * 2;
            const float bv0 = bv_s[lc], bv1 = bv_s[lc + 1];
            *(__half2*)(row0 + lc) = __floats2half2_rn(d[i][j][0] + av0 + bv0,
                                                       d[i][j][1] + av0 + bv1);
            *(__half2*)(row1 + lc) = __floats2half2_rn(d[i][j][2] + av1 + bv0,
                                                       d[i][j][3] + av1 + bv1);
        }
    }
}

// ---------------------------------------------------------------------------
// Kernel 3: transpose  out[b,l,m,c] = float(g_dm[b*8+c][l][m]); 2 m per thread.
// ---------------------------------------------------------------------------
__global__ void transpose_kernel(const __half* __restrict__ dm, float* __restrict__ out) {
    size_t e = (size_t)blockIdx.x * blockDim.x + threadIdx.x;   // over b*l*(m/2)
    int m2 = (int)(e & 511) * 2;
    int l  = (int)((e >> 9) & 1023);
    int b  = (int)(e >> 19);
    const __half* base = dm + (size_t)b * 8388608 + (size_t)l * 1024 + m2;
    float2 f[8];
#pragma unroll
    for (int c = 0; c < 8; c++)
        f[c] = __half22float2(*(const __half2*)(base + (size_t)c * 1048576));
    float4* op = (float4*)(out + e * 16);
    float4 o;
    o.x = f[0].x; o.y = f[1].x; o.z = f[2].x; o.w = f[3].x; op[0] = o;
    o.x = f[4].x; o.y = f[5].x; o.z = f[6].x; o.w = f[7].x; op[1] = o;
    o.x = f[0].y; o.y = f[1].y; o.z = f[2].y; o.w = f[3].y; op[2] = o;
    o.x = f[4].y; o.y = f[5].y; o.z = f[6].y; o.w = f[7].y; op[3] = o;
}

extern "C" void kernel_launch(void* const* d_in, const int* in_sizes, int n_in,
                              void* d_out, int out_size) {
    const float* start = (const float*)d_in[0];
    const float* endp  = (const float*)d_in[1];
    const float* v     = (const float*)d_in[2];
    float* out = (float*)d_out;

    static bool attr_set = false;
    if (!attr_set) {
        cudaFuncSetAttribute(gemm_mma, cudaFuncAttributeMaxDynamicSharedMemorySize, SMEM_DYN);
        attr_set = true;
    }

    __half* dm;
    cudaGetSymbolAddress((void**)&dm, g_dm);

    pack_kernel<<<dim3(128, BC_DIM), 256>>>(start, endp, v);
    gemm_mma<<<dim3(8, 8, BC_DIM), 256, SMEM_DYN>>>(dm);
    transpose_kernel<<<(1u << 20) / 256, 256>>>(dm, out);
}